// round 1
// baseline (speedup 1.0000x reference)
#include <cuda_runtime.h>
#include <math.h>

#define H 1024
#define E 512
#define A 512
#define L 512
#define V 50257

// ---------------- scratch (device globals; no allocations allowed) ----------
__device__ __align__(16) float g_cat[E + H];          // [embedded, h]     (1536)
__device__ __align__(16) float g_comb[E + H + A];     // [emb, attn, av]   (2048)
__device__ __align__(16) float g_scores[L];
__device__ __align__(16) float g_weights[L];
__device__ __align__(16) float g_part[8 * H];         // attn-apply partials
__device__ __align__(16) float g_x[H];
__device__ __align__(16) float g_gates[4 * H];
__device__ __align__(16) float g_h[H];

__device__ __forceinline__ float warp_sum(float v) {
#pragma unroll
    for (int o = 16; o > 0; o >>= 1) v += __shfl_down_sync(0xffffffffu, v, o);
    return v;
}

// ---------------- K0: build concat vectors ---------------------------------
__global__ void k_setup(const int* __restrict__ word,
                        const float* __restrict__ emb,
                        const float* __restrict__ h0,
                        const float* __restrict__ av) {
    int i = blockIdx.x * blockDim.x + threadIdx.x;   // 2048 threads
    if (i < E) {
        float e = emb[(size_t)word[0] * E + i];
        g_cat[i]  = e;
        g_comb[i] = e;
    } else if (i < E + H) {
        g_cat[i] = h0[i - E];
    } else if (i < E + H + A) {
        g_comb[i + (H - A)] = 0.0f;                  // unused slot guard (noop-ish)
        g_comb[E + H + (i - (E + H))] = av[i - (E + H)];
    }
}

// ---------------- K1: attn scores  (512 rows x 1536) -----------------------
__global__ void k_attn_score(const float* __restrict__ attn_W,
                             const float* __restrict__ attn_b) {
    int warp = (blockIdx.x * blockDim.x + threadIdx.x) >> 5;
    int lane = threadIdx.x & 31;
    if (warp >= L) return;
    const float4* wr = reinterpret_cast<const float4*>(attn_W) + (size_t)warp * (1536 / 4);
    const float4* c4 = reinterpret_cast<const float4*>(g_cat);
    float s = 0.f;
#pragma unroll
    for (int i = 0; i < 12; i++) {
        float4 w = wr[lane + 32 * i];
        float4 c = c4[lane + 32 * i];
        s += w.x * c.x + w.y * c.y + w.z * c.z + w.w * c.w;
    }
    s = warp_sum(s);
    if (lane == 0) g_scores[warp] = s + attn_b[warp];
}

// ---------------- K2: softmax over 512 -------------------------------------
__global__ void k_softmax(float* __restrict__ d_attn_out) {
    __shared__ float s_red[16];
    __shared__ float s_max, s_sum;
    int t = threadIdx.x;                              // 512 threads
    float v = g_scores[t];
    float m = v;
#pragma unroll
    for (int o = 16; o > 0; o >>= 1) m = fmaxf(m, __shfl_xor_sync(0xffffffffu, m, o));
    if ((t & 31) == 0) s_red[t >> 5] = m;
    __syncthreads();
    if (t == 0) {
        float mm = s_red[0];
#pragma unroll
        for (int i = 1; i < 16; i++) mm = fmaxf(mm, s_red[i]);
        s_max = mm;
    }
    __syncthreads();
    float e = expf(v - s_max);
    float su = e;
#pragma unroll
    for (int o = 16; o > 0; o >>= 1) su += __shfl_xor_sync(0xffffffffu, su, o);
    if ((t & 31) == 0) s_red[t >> 5] = su;
    __syncthreads();
    if (t == 0) {
        float ss = 0.f;
#pragma unroll
        for (int i = 0; i < 16; i++) ss += s_red[i];
        s_sum = ss;
    }
    __syncthreads();
    float w = e / s_sum;
    g_weights[t]  = w;
    d_attn_out[t] = w;
}

// ---------------- K3a: attn_applied partials (deterministic) ---------------
// grid (4 col-blocks of 256, 8 L-slices of 64), block 256
__global__ void k_attn_apply_part(const float* __restrict__ enc) {
    __shared__ float sw[64];
    int j  = blockIdx.x * 256 + threadIdx.x;
    int l0 = blockIdx.y * 64;
    if (threadIdx.x < 64) sw[threadIdx.x] = g_weights[l0 + threadIdx.x];
    __syncthreads();
    float s = 0.f;
#pragma unroll 8
    for (int l = 0; l < 64; l++) s += sw[l] * enc[(size_t)(l0 + l) * H + j];
    g_part[blockIdx.y * H + j] = s;
}

// ---------------- K3b: reduce partials into g_comb -------------------------
__global__ void k_attn_apply_reduce() {
    int j = blockIdx.x * blockDim.x + threadIdx.x;    // 1024 threads
    float s = 0.f;
#pragma unroll
    for (int p = 0; p < 8; p++) s += g_part[p * H + j];
    g_comb[E + j] = s;
}

// ---------------- K4: combine + relu (1024 rows x 2048) --------------------
__global__ void k_comb(const float* __restrict__ comb_W,
                       const float* __restrict__ comb_b) {
    int warp = (blockIdx.x * blockDim.x + threadIdx.x) >> 5;
    int lane = threadIdx.x & 31;
    if (warp >= H) return;
    const float4* wr = reinterpret_cast<const float4*>(comb_W) + (size_t)warp * (2048 / 4);
    const float4* c4 = reinterpret_cast<const float4*>(g_comb);
    float s = 0.f;
#pragma unroll
    for (int i = 0; i < 16; i++) {
        float4 w = wr[lane + 32 * i];
        float4 c = c4[lane + 32 * i];
        s += w.x * c.x + w.y * c.y + w.z * c.z + w.w * c.w;
    }
    s = warp_sum(s);
    if (lane == 0) g_x[warp] = fmaxf(s + comb_b[warp], 0.f);
}

// ---------------- K5: LSTM gates (4096 rows x (1024 + 1024)) ---------------
__global__ void k_gates(const float* __restrict__ W_ih,
                        const float* __restrict__ W_hh,
                        const float* __restrict__ b_ih,
                        const float* __restrict__ b_hh,
                        const float* __restrict__ h0) {
    int warp = (blockIdx.x * blockDim.x + threadIdx.x) >> 5;
    int lane = threadIdx.x & 31;
    if (warp >= 4 * H) return;
    const float4* wi = reinterpret_cast<const float4*>(W_ih) + (size_t)warp * (H / 4);
    const float4* wh = reinterpret_cast<const float4*>(W_hh) + (size_t)warp * (H / 4);
    const float4* x4 = reinterpret_cast<const float4*>(g_x);
    const float4* h4 = reinterpret_cast<const float4*>(h0);
    float s = 0.f;
#pragma unroll
    for (int i = 0; i < 8; i++) {
        float4 a = wi[lane + 32 * i];
        float4 b = x4[lane + 32 * i];
        s += a.x * b.x + a.y * b.y + a.z * b.z + a.w * b.w;
        float4 c = wh[lane + 32 * i];
        float4 d = h4[lane + 32 * i];
        s += c.x * d.x + c.y * d.y + c.z * d.z + c.w * d.w;
    }
    s = warp_sum(s);
    if (lane == 0) g_gates[warp] = s + b_ih[warp] + b_hh[warp];
}

// ---------------- K6: LSTM pointwise ----------------------------------------
__global__ void k_lstm(const float* __restrict__ c0,
                       float* __restrict__ d_h, float* __restrict__ d_c) {
    int k = blockIdx.x * blockDim.x + threadIdx.x;    // 1024 threads
    if (k >= H) return;
    float gi = g_gates[k];
    float gf = g_gates[H + k];
    float gg = g_gates[2 * H + k];
    float go = g_gates[3 * H + k];
    float si = 1.f / (1.f + expf(-gi));
    float sf = 1.f / (1.f + expf(-gf));
    float so = 1.f / (1.f + expf(-go));
    float cn = sf * c0[k] + si * tanhf(gg);
    float hn = so * tanhf(cn);
    g_h[k] = hn;
    d_h[k] = hn;
    d_c[k] = cn;
}

// ---------------- K7: logits (50257 rows x 1024) — the 206 MB read ---------
__global__ void k_logits(const float* __restrict__ out_W,
                         const float* __restrict__ out_b,
                         float* __restrict__ logits) {
    __shared__ float4 sh[H / 4];
    int t = threadIdx.x;                              // 256 threads, 8 warps
    sh[t] = reinterpret_cast<const float4*>(g_h)[t];
    __syncthreads();
    int row  = blockIdx.x * 8 + (t >> 5);
    int lane = t & 31;
    if (row >= V) return;
    const float4* wr = reinterpret_cast<const float4*>(out_W) + (size_t)row * (H / 4);
    float s = 0.f;
#pragma unroll
    for (int i = 0; i < 8; i++) {
        float4 w = wr[lane + 32 * i];
        float4 h = sh[lane + 32 * i];
        s += w.x * h.x + w.y * h.y + w.z * h.z + w.w * h.w;
    }
    s = warp_sum(s);
    if (lane == 0) logits[row] = s + out_b[row];
}

// ---------------- launch ----------------------------------------------------
extern "C" void kernel_launch(void* const* d_in, const int* in_sizes, int n_in,
                              void* d_out, int out_size) {
    (void)out_size;
    const int* word = (const int*)d_in[0];
    // enc_seq_len (scalar) may or may not be surfaced as an input; detect it.
    int k = (n_in >= 2 && in_sizes[1] == 1) ? 2 : 1;
    const float* av_emb  = (const float*)d_in[k + 0];
    const float* h0      = (const float*)d_in[k + 1];
    const float* c0      = (const float*)d_in[k + 2];
    const float* enc_out = (const float*)d_in[k + 3];
    const float* emb     = (const float*)d_in[k + 4];
    const float* attn_W  = (const float*)d_in[k + 5];
    const float* attn_b  = (const float*)d_in[k + 6];
    const float* comb_W  = (const float*)d_in[k + 7];
    const float* comb_b  = (const float*)d_in[k + 8];
    const float* W_ih    = (const float*)d_in[k + 9];
    const float* W_hh    = (const float*)d_in[k + 10];
    const float* b_ih    = (const float*)d_in[k + 11];
    const float* b_hh    = (const float*)d_in[k + 12];
    const float* out_W   = (const float*)d_in[k + 13];
    const float* out_b   = (const float*)d_in[k + 14];

    float* out = (float*)d_out;
    float* o_logits = out;              // [V]
    float* o_h      = out + V;          // [H]
    float* o_c      = out + V + H;      // [H]
    float* o_attn   = out + V + 2 * H;  // [L]

    k_setup<<<8, 256>>>(word, emb, h0, av_emb);
    k_attn_score<<<(L * 32) / 256, 256>>>(attn_W, attn_b);
    k_softmax<<<1, L>>>(o_attn);
    k_attn_apply_part<<<dim3(H / 256, 8), 256>>>(enc_out);
    k_attn_apply_reduce<<<H / 256, 256>>>();
    k_comb<<<(H * 32) / 256, 256>>>(comb_W, comb_b);
    k_gates<<<(4 * H * 32) / 256, 256>>>(W_ih, W_hh, b_ih, b_hh, h0);
    k_lstm<<<H / 256, 256>>>(c0, o_h, o_c);
    k_logits<<<(V + 7) / 8, 256>>>(out_W, out_b, o_logits);
}

// round 2
// speedup vs baseline: 1.1352x; 1.1352x over previous
#include <cuda_runtime.h>
#include <math.h>

#define H 1024
#define E 512
#define A 512
#define L 512
#define V 50257
#define NSLICE 16   // L-slices for attn apply

// ---------------- scratch (device globals; no allocations allowed) ----------
__device__ __align__(16) float g_scores[L];
__device__ __align__(16) float g_part[NSLICE * H];
__device__ __align__(16) float g_x[H];
__device__ __align__(16) float g_gates[4 * H];
__device__ __align__(16) float g_h[H];

__device__ __forceinline__ float warp_sum(float v) {
#pragma unroll
    for (int o = 16; o > 0; o >>= 1) v += __shfl_down_sync(0xffffffffu, v, o);
    return v;
}

// ---------------- K1: attn scores (512 rows x 1536), concat built in smem ---
__global__ __launch_bounds__(256) void k_attn_score(
        const int* __restrict__ word, const float* __restrict__ emb,
        const float* __restrict__ h0, const float* __restrict__ attn_W,
        const float* __restrict__ attn_b) {
    __shared__ float sc[E + H];
    int t = threadIdx.x;
    long wrow = (long)word[0] * E;
#pragma unroll
    for (int i = t; i < E + H; i += 256)
        sc[i] = (i < E) ? emb[wrow + i] : h0[i - E];
    __syncthreads();
    int row  = blockIdx.x * 8 + (t >> 5);
    int lane = t & 31;
    const float4* wr = reinterpret_cast<const float4*>(attn_W) + (size_t)row * (1536 / 4);
    const float4* c4 = reinterpret_cast<const float4*>(sc);
    float s = 0.f;
#pragma unroll
    for (int i = 0; i < 12; i++) {
        float4 w = __ldcs(&wr[lane + 32 * i]);
        float4 c = c4[lane + 32 * i];
        s += w.x * c.x + w.y * c.y + w.z * c.z + w.w * c.w;
    }
    s = warp_sum(s);
    if (lane == 0) g_scores[row] = s + attn_b[row];
}

// ---------------- K2: fused softmax + attn apply (partials) -----------------
// grid NSLICE blocks x 256 threads. Every block recomputes the identical
// softmax (deterministic), block 0 writes the attn-weights output.
__global__ __launch_bounds__(256) void k_attn_apply(
        const float* __restrict__ enc, float* __restrict__ d_attn_out) {
    __shared__ float sred[8];
    __shared__ float sw[L];
    __shared__ float sbc;
    int t = threadIdx.x, lane = t & 31, wid = t >> 5;

    float v0 = g_scores[t], v1 = g_scores[t + 256];
    // block max
    float m = fmaxf(v0, v1);
#pragma unroll
    for (int o = 16; o > 0; o >>= 1) m = fmaxf(m, __shfl_xor_sync(0xffffffffu, m, o));
    if (lane == 0) sred[wid] = m;
    __syncthreads();
    if (t == 0) {
        float mm = sred[0];
#pragma unroll
        for (int i = 1; i < 8; i++) mm = fmaxf(mm, sred[i]);
        sbc = mm;
    }
    __syncthreads();
    float bmax = sbc;
    float e0 = expf(v0 - bmax), e1 = expf(v1 - bmax);
    float su = e0 + e1;
#pragma unroll
    for (int o = 16; o > 0; o >>= 1) su += __shfl_xor_sync(0xffffffffu, su, o);
    __syncthreads();
    if (lane == 0) sred[wid] = su;
    __syncthreads();
    if (t == 0) {
        float ss = 0.f;
#pragma unroll
        for (int i = 0; i < 8; i++) ss += sred[i];
        sbc = ss;
    }
    __syncthreads();
    float inv = 1.0f / sbc;
    float w0 = e0 * inv, w1 = e1 * inv;
    sw[t] = w0;
    sw[t + 256] = w1;
    if (blockIdx.x == 0) { d_attn_out[t] = w0; d_attn_out[t + 256] = w1; }
    __syncthreads();

    // partial weighted sum over this block's 32 encoder rows, float4 columns
    int l0 = blockIdx.x * (L / NSLICE);
    const float4* e4 = reinterpret_cast<const float4*>(enc);
    float4 acc = make_float4(0.f, 0.f, 0.f, 0.f);
#pragma unroll
    for (int l = 0; l < L / NSLICE; l++) {
        float w = sw[l0 + l];
        float4 v = __ldcs(&e4[(size_t)(l0 + l) * (H / 4) + t]);
        acc.x += w * v.x; acc.y += w * v.y; acc.z += w * v.z; acc.w += w * v.w;
    }
    reinterpret_cast<float4*>(g_part)[blockIdx.x * (H / 4) + t] = acc;
}

// ---------------- K3: combine + relu (1024 x 2048), reduce fused ------------
__global__ __launch_bounds__(256) void k_comb(
        const int* __restrict__ word, const float* __restrict__ emb,
        const float* __restrict__ av, const float* __restrict__ comb_W,
        const float* __restrict__ comb_b) {
    __shared__ float sc[E + H + A];
    int t = threadIdx.x;
    long wrow = (long)word[0] * E;
#pragma unroll
    for (int i = t; i < E + H + A; i += 256) {
        float v;
        if (i < E) v = emb[wrow + i];
        else if (i < E + H) {
            int j = i - E;
            float s = 0.f;
#pragma unroll
            for (int p = 0; p < NSLICE; p++) s += g_part[p * H + j];
            v = s;
        } else v = av[i - (E + H)];
        sc[i] = v;
    }
    __syncthreads();
    int row  = blockIdx.x * 8 + (t >> 5);
    int lane = t & 31;
    const float4* wr = reinterpret_cast<const float4*>(comb_W) + (size_t)row * (2048 / 4);
    const float4* c4 = reinterpret_cast<const float4*>(sc);
    float s = 0.f;
#pragma unroll
    for (int i = 0; i < 16; i++) {
        float4 w = __ldcs(&wr[lane + 32 * i]);
        float4 c = c4[lane + 32 * i];
        s += w.x * c.x + w.y * c.y + w.z * c.z + w.w * c.w;
    }
    s = warp_sum(s);
    if (lane == 0) g_x[row] = fmaxf(s + comb_b[row], 0.f);
}

// ---------------- K4: LSTM gates (4096 x (1024+1024)) -----------------------
__global__ __launch_bounds__(256) void k_gates(
        const float* __restrict__ W_ih, const float* __restrict__ W_hh,
        const float* __restrict__ b_ih, const float* __restrict__ b_hh,
        const float* __restrict__ h0) {
    __shared__ float4 sx[H / 4], sh[H / 4];
    int t = threadIdx.x;
    sx[t] = reinterpret_cast<const float4*>(g_x)[t];
    sh[t] = reinterpret_cast<const float4*>(h0)[t];
    __syncthreads();
    int row  = blockIdx.x * 8 + (t >> 5);
    int lane = t & 31;
    const float4* wi = reinterpret_cast<const float4*>(W_ih) + (size_t)row * (H / 4);
    const float4* wh = reinterpret_cast<const float4*>(W_hh) + (size_t)row * (H / 4);
    float s = 0.f;
#pragma unroll
    for (int i = 0; i < 8; i++) {
        float4 a = __ldcs(&wi[lane + 32 * i]);
        float4 b = sx[lane + 32 * i];
        s += a.x * b.x + a.y * b.y + a.z * b.z + a.w * b.w;
        float4 c = __ldcs(&wh[lane + 32 * i]);
        float4 d = sh[lane + 32 * i];
        s += c.x * d.x + c.y * d.y + c.z * d.z + c.w * d.w;
    }
    s = warp_sum(s);
    if (lane == 0) g_gates[row] = s + b_ih[row] + b_hh[row];
}

// ---------------- K5: LSTM pointwise (single block) -------------------------
__global__ __launch_bounds__(1024) void k_lstm(
        const float* __restrict__ c0, float* __restrict__ d_h,
        float* __restrict__ d_c) {
    int k = threadIdx.x;
    float gi = g_gates[k];
    float gf = g_gates[H + k];
    float gg = g_gates[2 * H + k];
    float go = g_gates[3 * H + k];
    float si = 1.f / (1.f + expf(-gi));
    float sf = 1.f / (1.f + expf(-gf));
    float so = 1.f / (1.f + expf(-go));
    float cn = sf * c0[k] + si * tanhf(gg);
    float hn = so * tanhf(cn);
    g_h[k] = hn;
    d_h[k] = hn;
    d_c[k] = cn;
}

// ---------------- K6: logits (50257 x 1024) — the 206 MB stream -------------
__global__ __launch_bounds__(256) void k_logits(
        const float* __restrict__ out_W, const float* __restrict__ out_b,
        float* __restrict__ logits) {
    __shared__ float4 sh[H / 4];
    int t = threadIdx.x;
    sh[t] = reinterpret_cast<const float4*>(g_h)[t];
    __syncthreads();
    int row  = blockIdx.x * 8 + (t >> 5);
    int lane = t & 31;
    if (row >= V) return;
    const float4* wr = reinterpret_cast<const float4*>(out_W) + (size_t)row * (H / 4);
    float s = 0.f;
#pragma unroll
    for (int i = 0; i < 8; i++) {
        float4 w = __ldcs(&wr[lane + 32 * i]);
        float4 h = sh[lane + 32 * i];
        s += w.x * h.x + w.y * h.y + w.z * h.z + w.w * h.w;
    }
    s = warp_sum(s);
    if (lane == 0) logits[row] = s + out_b[row];
}

// ---------------- launch ----------------------------------------------------
extern "C" void kernel_launch(void* const* d_in, const int* in_sizes, int n_in,
                              void* d_out, int out_size) {
    (void)out_size;
    const int* word = (const int*)d_in[0];
    int k = (n_in >= 2 && in_sizes[1] == 1) ? 2 : 1;
    const float* av_emb  = (const float*)d_in[k + 0];
    const float* h0      = (const float*)d_in[k + 1];
    const float* c0      = (const float*)d_in[k + 2];
    const float* enc_out = (const float*)d_in[k + 3];
    const float* emb     = (const float*)d_in[k + 4];
    const float* attn_W  = (const float*)d_in[k + 5];
    const float* attn_b  = (const float*)d_in[k + 6];
    const float* comb_W  = (const float*)d_in[k + 7];
    const float* comb_b  = (const float*)d_in[k + 8];
    const float* W_ih    = (const float*)d_in[k + 9];
    const float* W_hh    = (const float*)d_in[k + 10];
    const float* b_ih    = (const float*)d_in[k + 11];
    const float* b_hh    = (const float*)d_in[k + 12];
    const float* out_W   = (const float*)d_in[k + 13];
    const float* out_b   = (const float*)d_in[k + 14];

    float* out = (float*)d_out;
    float* o_logits = out;              // [V]
    float* o_h      = out + V;          // [H]
    float* o_c      = out + V + H;      // [H]
    float* o_attn   = out + V + 2 * H;  // [L]

    k_attn_score<<<L / 8, 256>>>(word, emb, h0, attn_W, attn_b);
    k_attn_apply<<<NSLICE, 256>>>(enc_out, o_attn);
    k_comb<<<H / 8, 256>>>(word, emb, av_emb, comb_W, comb_b);
    k_gates<<<(4 * H) / 8, 256>>>(W_ih, W_hh, b_ih, b_hh, h0);
    k_lstm<<<1, 1024>>>(c0, o_h, o_c);
    k_logits<<<(V + 7) / 8, 256>>>(out_W, out_b, o_logits);
}